// round 12
// baseline (speedup 1.0000x reference)
#include <cuda_runtime.h>
#include <cstdint>

#define Bb 512
#define Tt 50
#define Ff 2048
#define H1 1024
#define H2 1024
#define Ss 16
#define SPLITK 4   // GEMM1: 4 contiguous K-chunks of 512, ascending combine (validated R8)

__device__ float g_rate[Bb * Ff];
__device__ float g_part1[SPLITK * Bb * H1];
__device__ float g_cur1[Bb * H1];
__device__ float g_spk1[Ss * Bb * H1];
__device__ float g_cur2[Ss * Bb * H2];

// ---------------------------------------------------------------------------
// 1) Encoder: rate[b,f] = count_t( sigmoid(x) > 0.5 ) * (1/50).
//    Cutoff x > 2^-23 (XLA logistic tanh-form + EmitTanh small-x shortcut).
//    THIS ROUND: mean's divide-by-50 modeled as multiply by fl(0.02)
//    (XLA algsimp rewrites divide-by-constant into multiply-by-reciprocal).
// ---------------------------------------------------------------------------
__global__ void rate_kernel(const float* __restrict__ x) {
    const float CUT = 1.1920928955078125e-7f;   // 2^-23
    const float INV50 = 0.02f;                  // fl(1/50), the XLA reciprocal
    int idx = blockIdx.x * blockDim.x + threadIdx.x;
    int b  = idx >> 9;
    int f4 = idx & 511;
    const float4* p = reinterpret_cast<const float4*>(x) + (size_t)b * Tt * (Ff / 4) + f4;
    int c0 = 0, c1 = 0, c2 = 0, c3 = 0;
#pragma unroll 10
    for (int t = 0; t < Tt; t++) {
        float4 v = p[(size_t)t * (Ff / 4)];
        c0 += (v.x > CUT); c1 += (v.y > CUT); c2 += (v.z > CUT); c3 += (v.w > CUT);
    }
    float4 r;
    r.x = __fmul_rn((float)c0, INV50);
    r.y = __fmul_rn((float)c1, INV50);
    r.z = __fmul_rn((float)c2, INV50);
    r.w = __fmul_rn((float)c3, INV50);
    reinterpret_cast<float4*>(g_rate)[idx] = r;
}

// ---------------------------------------------------------------------------
// GEMM1 split-K partials: 64x64 tile, BK=8. Slice z covers k in
// [z*kLen, (z+1)*kLen): sequential ascending-k FFMA from 0.
// ---------------------------------------------------------------------------
__global__ void __launch_bounds__(256, 2)
sgemm_nt_64_part(const float* __restrict__ A, const float* __restrict__ Bm,
                 float* __restrict__ Cpart, int K, int kLen, int N)
{
    __shared__ __align__(16) float As[8][64];
    __shared__ __align__(16) float Bs[8][64];

    const int tid  = threadIdx.x;
    const int tx   = tid & 15;
    const int ty   = tid >> 4;
    const int lrow = tid >> 2;
    const int lcol = (tid & 3) * 2;
    const int kOff = blockIdx.z * kLen;

    const float* Ap = A + (size_t)(blockIdx.y * 64 + lrow) * K + kOff + lcol;
    const float* Bp = Bm + (size_t)(blockIdx.x * 64 + lrow) * K + kOff + lcol;
    float* C = Cpart + (size_t)blockIdx.z * Bb * H1;

    float acc[4][4];
#pragma unroll
    for (int i = 0; i < 4; i++)
#pragma unroll
        for (int j = 0; j < 4; j++) acc[i][j] = 0.0f;

    float2 av = *reinterpret_cast<const float2*>(Ap);
    float2 bv = *reinterpret_cast<const float2*>(Bp);

    const int kIters = kLen / 8;
    for (int it = 0; it < kIters; ++it) {
        __syncthreads();
        As[lcol + 0][lrow] = av.x; As[lcol + 1][lrow] = av.y;
        Bs[lcol + 0][lrow] = bv.x; Bs[lcol + 1][lrow] = bv.y;
        __syncthreads();
        if (it + 1 < kIters) {
            av = *reinterpret_cast<const float2*>(Ap + (it + 1) * 8);
            bv = *reinterpret_cast<const float2*>(Bp + (it + 1) * 8);
        }
#pragma unroll
        for (int k = 0; k < 8; k++) {
            float a[4], b[4];
            *reinterpret_cast<float4*>(a) = *reinterpret_cast<const float4*>(&As[k][ty * 4]);
            *reinterpret_cast<float4*>(b) = *reinterpret_cast<const float4*>(&Bs[k][tx * 4]);
#pragma unroll
            for (int i = 0; i < 4; i++)
#pragma unroll
                for (int j = 0; j < 4; j++)
                    acc[i][j] = __fmaf_rn(a[i], b[j], acc[i][j]);
        }
    }

    const int colBase = blockIdx.x * 64 + tx * 4;
#pragma unroll
    for (int i = 0; i < 4; i++) {
        int row = blockIdx.y * 64 + ty * 4 + i;
        *reinterpret_cast<float4*>(&C[(size_t)row * N + colBase]) =
            make_float4(acc[i][0], acc[i][1], acc[i][2], acc[i][3]);
    }
}

// ---------------------------------------------------------------------------
// Split-K combine: ascending linear order, then + bias (separate fp32 add).
// ---------------------------------------------------------------------------
__global__ void combine1_kernel(const float* __restrict__ b1) {
    int idx = blockIdx.x * blockDim.x + threadIdx.x;
    const int BH = Bb * H1;
    float s = g_part1[idx];
    s = __fadd_rn(s, g_part1[idx + BH]);
    s = __fadd_rn(s, g_part1[idx + 2 * BH]);
    s = __fadd_rn(s, g_part1[idx + 3 * BH]);
    g_cur1[idx] = __fadd_rn(s, b1[idx & (H1 - 1)]);
}

// ---------------------------------------------------------------------------
// GEMM2: sequential-K single-accumulator FFMA, 128x128 tile, BK=8.
// ---------------------------------------------------------------------------
__global__ void __launch_bounds__(256, 2)
sgemm_nt(const float* __restrict__ A, const float* __restrict__ Bm,
         const float* __restrict__ bias, float* __restrict__ C,
         int K, int N)
{
    __shared__ __align__(16) float As[8][128];
    __shared__ __align__(16) float Bs[8][128];

    const int tid  = threadIdx.x;
    const int lrow = tid >> 1;
    const int lcol = (tid & 1) * 4;
    const int tx   = tid & 15;
    const int ty   = tid >> 4;

    const float* Aptr = A + (size_t)(blockIdx.y * 128 + lrow) * K + lcol;
    const float* Bptr = Bm + (size_t)(blockIdx.x * 128 + lrow) * K + lcol;

    float acc[8][8];
#pragma unroll
    for (int i = 0; i < 8; i++)
#pragma unroll
        for (int j = 0; j < 8; j++) acc[i][j] = 0.0f;

    float4 av = *reinterpret_cast<const float4*>(Aptr);
    float4 bv = *reinterpret_cast<const float4*>(Bptr);

    const int kIters = K / 8;
    for (int it = 0; it < kIters; ++it) {
        __syncthreads();
        As[lcol + 0][lrow] = av.x; As[lcol + 1][lrow] = av.y;
        As[lcol + 2][lrow] = av.z; As[lcol + 3][lrow] = av.w;
        Bs[lcol + 0][lrow] = bv.x; Bs[lcol + 1][lrow] = bv.y;
        Bs[lcol + 2][lrow] = bv.z; Bs[lcol + 3][lrow] = bv.w;
        __syncthreads();
        if (it + 1 < kIters) {
            av = *reinterpret_cast<const float4*>(Aptr + (it + 1) * 8);
            bv = *reinterpret_cast<const float4*>(Bptr + (it + 1) * 8);
        }
#pragma unroll
        for (int k = 0; k < 8; k++) {
            float a[8], b[8];
            *reinterpret_cast<float4*>(&a[0]) = *reinterpret_cast<const float4*>(&As[k][ty * 4]);
            *reinterpret_cast<float4*>(&a[4]) = *reinterpret_cast<const float4*>(&As[k][64 + ty * 4]);
            *reinterpret_cast<float4*>(&b[0]) = *reinterpret_cast<const float4*>(&Bs[k][tx * 4]);
            *reinterpret_cast<float4*>(&b[4]) = *reinterpret_cast<const float4*>(&Bs[k][64 + tx * 4]);
#pragma unroll
            for (int i = 0; i < 8; i++)
#pragma unroll
                for (int j = 0; j < 8; j++)
                    acc[i][j] = __fmaf_rn(a[i], b[j], acc[i][j]);
        }
    }

    float bfr[8];
    *reinterpret_cast<float4*>(&bfr[0]) =
        *reinterpret_cast<const float4*>(&bias[blockIdx.x * 128 + tx * 4]);
    *reinterpret_cast<float4*>(&bfr[4]) =
        *reinterpret_cast<const float4*>(&bias[blockIdx.x * 128 + 64 + tx * 4]);
    const int colBase = blockIdx.x * 128;
#pragma unroll
    for (int i = 0; i < 8; i++) {
        int row = blockIdx.y * 128 + ((i < 4) ? (ty * 4 + i) : (64 + ty * 4 + (i - 4)));
        float4 o0, o1;
        o0.x = __fadd_rn(acc[i][0], bfr[0]); o0.y = __fadd_rn(acc[i][1], bfr[1]);
        o0.z = __fadd_rn(acc[i][2], bfr[2]); o0.w = __fadd_rn(acc[i][3], bfr[3]);
        o1.x = __fadd_rn(acc[i][4], bfr[4]); o1.y = __fadd_rn(acc[i][5], bfr[5]);
        o1.z = __fadd_rn(acc[i][6], bfr[6]); o1.w = __fadd_rn(acc[i][7], bfr[7]);
        *reinterpret_cast<float4*>(&C[(size_t)row * N + colBase + tx * 4]) = o0;
        *reinterpret_cast<float4*>(&C[(size_t)row * N + colBase + 64 + tx * 4]) = o1;
    }
}

// ---------------------------------------------------------------------------
// LIF scans: mem = sub(fma(0.9, mem, c), reset)
// ---------------------------------------------------------------------------
__global__ void scan1_kernel() {
    int idx = blockIdx.x * blockDim.x + threadIdx.x;
    const int BH = Bb * H1;
    float c = g_cur1[idx];
    float mem = 0.0f;
#pragma unroll
    for (int s = 0; s < Ss; s++) {
        float reset = (mem > 1.0f) ? 1.0f : 0.0f;
        mem = __fsub_rn(__fmaf_rn(0.9f, mem, c), reset);
        g_spk1[s * BH + idx] = (mem > 1.0f) ? 1.0f : 0.0f;
    }
}

__global__ void scan2_kernel(float* __restrict__ out) {
    int idx = blockIdx.x * blockDim.x + threadIdx.x;
    const int BH = Bb * H2;
    float mem = 0.0f;
#pragma unroll
    for (int s = 0; s < Ss; s++) {
        float c = g_cur2[s * BH + idx];
        float reset = (mem > 1.0f) ? 1.0f : 0.0f;
        mem = __fsub_rn(__fmaf_rn(0.9f, mem, c), reset);
        out[s * BH + idx] = (mem > 1.0f) ? 1.0f : 0.0f;
    }
}

// ---------------------------------------------------------------------------
extern "C" void kernel_launch(void* const* d_in, const int* in_sizes, int n_in,
                              void* d_out, int out_size)
{
    const float* x  = (const float*)d_in[0];
    const float* W1 = (const float*)d_in[1];
    const float* b1 = (const float*)d_in[2];
    const float* W2 = (const float*)d_in[3];
    const float* b2 = (const float*)d_in[4];
    float* out = (float*)d_out;

    float *rate, *part1, *spk1, *cur2;
    cudaGetSymbolAddress((void**)&rate,  g_rate);
    cudaGetSymbolAddress((void**)&part1, g_part1);
    cudaGetSymbolAddress((void**)&spk1,  g_spk1);
    cudaGetSymbolAddress((void**)&cur2,  g_cur2);

    rate_kernel<<<(Bb * Ff / 4) / 256, 256>>>(x);

    {   // GEMM1: 4 split-K slices of 512, ascending combine + b1
        dim3 grid(H1 / 64, Bb / 64, SPLITK);
        sgemm_nt_64_part<<<grid, 256>>>(rate, W1, part1, Ff, Ff / SPLITK, H1);
    }
    combine1_kernel<<<(Bb * H1) / 256, 256>>>(b1);

    scan1_kernel<<<(Bb * H1) / 256, 256>>>();

    {   // GEMM2: sequential-K, 512 CTAs
        dim3 grid(H2 / 128, (Ss * Bb) / 128);
        sgemm_nt<<<grid, 256>>>(spk1, W2, b2, cur2, H1, H2);
    }

    scan2_kernel<<<(Bb * H2) / 256, 256>>>(out);
}